// round 4
// baseline (speedup 1.0000x reference)
#include <cuda_runtime.h>
#include <math.h>
#include <stdint.h>

#define BSZ 131072
#define TTR 10
#define KF 304          // padded feature dim (300 -> 304)
#define HID 1024
#define NUM_ELEM 118
#define EMB 10

// ---- scratch (device globals; no runtime allocation) ----
__device__ float g_feat[(size_t)BSZ * KF];   // tf32-rounded features, padded
__device__ float g_h1[(size_t)BSZ * HID];    // tf32-rounded relu(layer1)
__device__ float g_w1p[(size_t)KF * HID];    // W1 zero-padded + tf32-rounded
__device__ float g_w2r[(size_t)HID * HID];   // W2 tf32-rounded

// ---- helpers ----
__device__ __forceinline__ uint32_t f2tf(float x) {
    uint32_t r;
    asm("cvt.rna.tf32.f32 %0, %1;" : "=r"(r) : "f"(x));
    return r;
}
__device__ __forceinline__ float rnd_tf32(float x) { return __uint_as_float(f2tf(x)); }

__device__ __forceinline__ void mma8(float* c, const uint32_t* a,
                                     uint32_t b0, uint32_t b1) {
    asm volatile(
        "mma.sync.aligned.m16n8k8.row.col.f32.tf32.tf32.f32 "
        "{%0,%1,%2,%3}, {%4,%5,%6,%7}, {%8,%9}, {%0,%1,%2,%3};"
        : "+f"(c[0]), "+f"(c[1]), "+f"(c[2]), "+f"(c[3])
        : "r"(a[0]), "r"(a[1]), "r"(a[2]), "r"(a[3]), "r"(b0), "r"(b1));
}

__device__ __forceinline__ void cp16(float* dst, const float* src) {
    uint32_t d = (uint32_t)__cvta_generic_to_shared(dst);
    asm volatile("cp.async.ca.shared.global [%0], [%1], 16;" :: "r"(d), "l"(src));
}
#define CP_COMMIT() asm volatile("cp.async.commit_group;")
#define CP_WAIT1()  asm volatile("cp.async.wait_group 1;")
#define CP_WAIT0()  asm volatile("cp.async.wait_group 0;")

// ---- prep: pad + tf32-round W1; round W2 ----
__global__ void pad_w1_kernel(const float* __restrict__ W1, float* __restrict__ w1p) {
    int i = blockIdx.x * blockDim.x + threadIdx.x;
    if (i >= KF * HID) return;
    int row = i >> 10;
    w1p[i] = (row < 300) ? rnd_tf32(W1[i]) : 0.0f;
}
__global__ void prep_w2_kernel(const float* __restrict__ W2, float* __restrict__ w2r) {
    int i = blockIdx.x * blockDim.x + threadIdx.x;
    if (i < HID * HID) w2r[i] = rnd_tf32(W2[i]);
}
__global__ void init_out_kernel(float* __restrict__ out, const float* __restrict__ b3) {
    int i = blockIdx.x * blockDim.x + threadIdx.x;
    if (i < BSZ) out[i] = b3[0];
}

// ---- features [B, 304], tf32-rounded ----
__global__ void feat_kernel(const float* __restrict__ structures,
                            const float* __restrict__ E,
                            float* __restrict__ feat) {
    __shared__ float sE[NUM_ELEM * EMB];
    for (int i = threadIdx.x; i < NUM_ELEM * EMB; i += blockDim.x)
        sE[i] = rnd_tf32(E[i]);
    __syncthreads();

    int gidx = blockIdx.x * blockDim.x + threadIdx.x;
    if (gidx >= BSZ * TTR) return;
    int b = gidx / TTR;
    int t = gidx % TTR;

    const float* s = structures + ((size_t)b * TTR + t) * 3;
    int ii = (int)s[0];
    int jj = (int)s[1];
    float d = s[2];
    bool mi = (ii != 0);
    bool mj = (jj != 0);

    float* o = feat + (size_t)b * KF + t * 30;
    #pragma unroll
    for (int c = 0; c < 10; c++) o[c] = mi ? sE[ii * EMB + c] : 0.0f;
    #pragma unroll
    for (int c = 0; c < 10; c++) o[10 + c] = mj ? sE[jj * EMB + c] : 0.0f;
    #pragma unroll
    for (int c = 0; c < 10; c++) {
        float diff = 0.7f * (float)(c + 1) - d;
        o[20 + c] = mi ? rnd_tf32(expf(-diff * diff)) : 0.0f;
    }
    if (t == 0) {
        float* p = feat + (size_t)b * KF + 300;
        p[0] = 0.0f; p[1] = 0.0f; p[2] = 0.0f; p[3] = 0.0f;
    }
}

// ---- fused GEMM (512 threads, 16 warps, warp tile 32x64) ----
// C = relu(A@B + bias); EPI=0 stores tf32-rounded [*,1024]; EPI=1 fuses W3 dot.
#define BM 128
#define BN 256
#define BK 16
#define ASTR 20
#define BSTR 264
#define SMEM_BYTES ((2*BM*ASTR + 2*BK*BSTR + 2*BN) * 4)

template <int EPI>
__global__ void __launch_bounds__(512, 1) gemm_kernel(
    const float* __restrict__ A, int lda, int K,
    const float* __restrict__ Bw,     // [K, 1024] row-major, tf32-rounded
    const float* __restrict__ bias,   // [1024]
    const float* __restrict__ W3,     // [1024] (EPI==1)
    float* __restrict__ Cout)
{
    extern __shared__ float smem[];
    float* As    = smem;                      // [2][BM][ASTR]
    float* Bs    = smem + 2 * BM * ASTR;      // [2][BK][BSTR]
    float* sBias = Bs + 2 * BK * BSTR;        // [BN]
    float* sW3   = sBias + BN;                // [BN]

    const int tid  = threadIdx.x;
    const int lane = tid & 31;
    const int wid  = tid >> 5;
    const int wm   = wid & 3;       // 4 warp rows of 32
    const int wn   = wid >> 2;      // 4 warp cols of 64
    const int g    = lane >> 2;     // groupID (0..7)
    const int t    = lane & 3;      // thread in group (0..3)
    const int m0   = blockIdx.y * BM;
    const int n0   = blockIdx.x * BN;

    float acc[2][8][4];
    #pragma unroll
    for (int i = 0; i < 2; i++)
        #pragma unroll
        for (int j = 0; j < 8; j++)
            #pragma unroll
            for (int k = 0; k < 4; k++) acc[i][j][k] = 0.0f;

    const int KT = K / BK;

    auto issue = [&](int kt, int buf) {
        int k0 = kt * BK;
        {                                          // A tile: 512 x 16B
            int row = tid >> 2, kv = tid & 3;
            cp16(&As[buf * BM * ASTR + row * ASTR + kv * 4],
                 A + (size_t)(m0 + row) * lda + k0 + kv * 4);
        }
        #pragma unroll
        for (int i = 0; i < 2; i++) {              // B tile: 1024 x 16B
            int l = tid + i * 512;
            int row = l >> 6, c4 = l & 63;
            cp16(&Bs[buf * BK * BSTR + row * BSTR + c4 * 4],
                 Bw + (size_t)(k0 + row) * HID + n0 + c4 * 4);
        }
    };

    auto compute = [&](int buf) {
        const uint32_t* Ab = (const uint32_t*)&As[buf * BM * ASTR];
        const uint32_t* Bb = (const uint32_t*)&Bs[buf * BK * BSTR];
        #pragma unroll
        for (int ks = 0; ks < BK; ks += 8) {
            uint32_t a[2][4];
            #pragma unroll
            for (int ms = 0; ms < 2; ms++) {
                int r = wm * 32 + ms * 16;
                a[ms][0] = Ab[(r + g)     * ASTR + ks + t];
                a[ms][1] = Ab[(r + g + 8) * ASTR + ks + t];
                a[ms][2] = Ab[(r + g)     * ASTR + ks + t + 4];
                a[ms][3] = Ab[(r + g + 8) * ASTR + ks + t + 4];
            }
            #pragma unroll
            for (int ns = 0; ns < 8; ns++) {
                int c = wn * 64 + ns * 8 + g;
                uint32_t b0 = Bb[(ks + t)     * BSTR + c];
                uint32_t b1 = Bb[(ks + t + 4) * BSTR + c];
                mma8(acc[0][ns], a[0], b0, b1);
                mma8(acc[1][ns], a[1], b0, b1);
            }
        }
    };

    issue(0, 0);
    CP_COMMIT();
    for (int kt = 0; kt < KT; kt++) {
        int cur = kt & 1;
        if (kt + 1 < KT) { issue(kt + 1, cur ^ 1); CP_COMMIT(); CP_WAIT1(); }
        else             { CP_WAIT0(); }
        __syncthreads();
        compute(cur);
        __syncthreads();
    }

    // epilogue
    for (int i = tid; i < BN; i += 512) {
        sBias[i] = bias[n0 + i];
        if (EPI == 1) sW3[i] = W3[n0 + i];
    }
    __syncthreads();

    if (EPI == 0) {
        #pragma unroll
        for (int ms = 0; ms < 2; ms++) {
            int row = m0 + wm * 32 + ms * 16 + g;
            #pragma unroll
            for (int ns = 0; ns < 8; ns++) {
                int cl  = wn * 64 + ns * 8 + t * 2;
                int col = n0 + cl;
                float2 v0, v1;
                v0.x = rnd_tf32(fmaxf(acc[ms][ns][0] + sBias[cl],     0.0f));
                v0.y = rnd_tf32(fmaxf(acc[ms][ns][1] + sBias[cl + 1], 0.0f));
                v1.x = rnd_tf32(fmaxf(acc[ms][ns][2] + sBias[cl],     0.0f));
                v1.y = rnd_tf32(fmaxf(acc[ms][ns][3] + sBias[cl + 1], 0.0f));
                *(float2*)&Cout[(size_t)row * HID + col]       = v0;
                *(float2*)&Cout[(size_t)(row + 8) * HID + col] = v1;
            }
        }
    } else {
        float racc[2][2] = {{0.0f, 0.0f}, {0.0f, 0.0f}};
        #pragma unroll
        for (int ms = 0; ms < 2; ms++) {
            #pragma unroll
            for (int ns = 0; ns < 8; ns++) {
                int cl = wn * 64 + ns * 8 + t * 2;
                racc[ms][0] += fmaxf(acc[ms][ns][0] + sBias[cl],     0.0f) * sW3[cl]
                             + fmaxf(acc[ms][ns][1] + sBias[cl + 1], 0.0f) * sW3[cl + 1];
                racc[ms][1] += fmaxf(acc[ms][ns][2] + sBias[cl],     0.0f) * sW3[cl]
                             + fmaxf(acc[ms][ns][3] + sBias[cl + 1], 0.0f) * sW3[cl + 1];
            }
        }
        #pragma unroll
        for (int ms = 0; ms < 2; ms++) {
            #pragma unroll
            for (int rp = 0; rp < 2; rp++) {
                float p = racc[ms][rp];
                p += __shfl_xor_sync(0xffffffffu, p, 1);
                p += __shfl_xor_sync(0xffffffffu, p, 2);
                if (t == 0)
                    atomicAdd(&Cout[m0 + wm * 32 + ms * 16 + rp * 8 + g], p);
            }
        }
    }
}

// ---- launch ----
extern "C" void kernel_launch(void* const* d_in, const int* in_sizes, int n_in,
                              void* d_out, int out_size) {
    const float* structures = (const float*)d_in[0];
    const float* E  = (const float*)d_in[1];
    const float* W1 = (const float*)d_in[2];
    const float* b1 = (const float*)d_in[3];
    const float* W2 = (const float*)d_in[4];
    const float* b2 = (const float*)d_in[5];
    const float* W3 = (const float*)d_in[6];
    const float* b3 = (const float*)d_in[7];
    float* out = (float*)d_out;

    float *feat, *h1, *w1p, *w2r;
    cudaGetSymbolAddress((void**)&feat, g_feat);
    cudaGetSymbolAddress((void**)&h1,   g_h1);
    cudaGetSymbolAddress((void**)&w1p,  g_w1p);
    cudaGetSymbolAddress((void**)&w2r,  g_w2r);

    cudaFuncSetAttribute(gemm_kernel<0>, cudaFuncAttributeMaxDynamicSharedMemorySize, SMEM_BYTES);
    cudaFuncSetAttribute(gemm_kernel<1>, cudaFuncAttributeMaxDynamicSharedMemorySize, SMEM_BYTES);

    pad_w1_kernel<<<(KF * HID + 255) / 256, 256>>>(W1, w1p);
    prep_w2_kernel<<<(HID * HID + 255) / 256, 256>>>(W2, w2r);
    init_out_kernel<<<(BSZ + 255) / 256, 256>>>(out, b3);
    feat_kernel<<<(BSZ * TTR + 255) / 256, 256>>>(structures, E, feat);

    dim3 grid(HID / BN, BSZ / BM);  // (4, 1024)
    gemm_kernel<0><<<grid, 512, SMEM_BYTES>>>(feat, KF, KF, w1p, b1, nullptr, h1);
    gemm_kernel<1><<<grid, 512, SMEM_BYTES>>>(h1, HID, HID, w2r, b2, W3, out);
}

// round 5
// speedup vs baseline: 1.8081x; 1.8081x over previous
#include <cuda_runtime.h>
#include <cuda_fp16.h>
#include <math.h>
#include <stdint.h>

#define BSZ 131072
#define TTR 10
#define KF 320          // padded feature dim (300 -> 320, multiple of 32)
#define HID 1024
#define NUM_ELEM 118

// ---- scratch (device globals; no runtime allocation) ----
__device__ __half g_feat[(size_t)BSZ * KF];   // [B, 320] half, padded
__device__ __half g_h1[(size_t)BSZ * HID];    // relu(layer1) as half
__device__ __half g_w1t[(size_t)HID * KF];    // W1^T [n][k], half, zero-padded
__device__ __half g_w2t[(size_t)HID * HID];   // W2^T [n][k], half

// ---- helpers ----
__device__ __forceinline__ void mma16(float* c, const uint32_t* a,
                                      uint32_t b0, uint32_t b1) {
    asm volatile(
        "mma.sync.aligned.m16n8k16.row.col.f32.f16.f16.f32 "
        "{%0,%1,%2,%3}, {%4,%5,%6,%7}, {%8,%9}, {%0,%1,%2,%3};"
        : "+f"(c[0]), "+f"(c[1]), "+f"(c[2]), "+f"(c[3])
        : "r"(a[0]), "r"(a[1]), "r"(a[2]), "r"(a[3]), "r"(b0), "r"(b1));
}
__device__ __forceinline__ void ldsm4(uint32_t* r, uint32_t addr) {
    asm volatile("ldmatrix.sync.aligned.m8n8.x4.shared.b16 {%0,%1,%2,%3}, [%4];"
                 : "=r"(r[0]), "=r"(r[1]), "=r"(r[2]), "=r"(r[3]) : "r"(addr));
}
__device__ __forceinline__ void cp16(uint32_t dst, const void* src) {
    asm volatile("cp.async.cg.shared.global [%0], [%1], 16;" :: "r"(dst), "l"(src));
}
#define CP_COMMIT() asm volatile("cp.async.commit_group;")
#define CP_WAIT1()  asm volatile("cp.async.wait_group 1;")
#define CP_WAIT0()  asm volatile("cp.async.wait_group 0;")

// ---- prep: transpose weights to [n][k] half ----
__global__ void prep_w1t_kernel(const float* __restrict__ W1, __half* __restrict__ w1t) {
    int i = blockIdx.x * blockDim.x + threadIdx.x;      // i = n*KF + k
    if (i >= HID * KF) return;
    int n = i / KF, k = i - n * KF;
    w1t[i] = (k < 300) ? __float2half(W1[(size_t)k * HID + n]) : __half(0.0f);
}
__global__ void prep_w2t_kernel(const float* __restrict__ W2, __half* __restrict__ w2t) {
    int i = blockIdx.x * blockDim.x + threadIdx.x;      // i = n*HID + k
    if (i >= HID * HID) return;
    int n = i >> 10, k = i & 1023;
    w2t[i] = __float2half(W2[(size_t)k * HID + n]);
}
__global__ void init_out_kernel(float* __restrict__ out, const float* __restrict__ b3) {
    int i = blockIdx.x * blockDim.x + threadIdx.x;
    if (i < BSZ) out[i] = b3[0];
}

// ---- features: flat element-indexed, coalesced half stores ----
__global__ void feat_kernel(const float* __restrict__ structures,
                            const float* __restrict__ E,
                            __half* __restrict__ feat) {
    int idx = blockIdx.x * blockDim.x + threadIdx.x;
    if (idx >= BSZ * KF) return;
    int b = idx / KF;
    int c = idx - b * KF;
    float v = 0.0f;
    if (c < 300) {
        int t = c / 30;
        int r = c - t * 30;
        const float* s = structures + (size_t)b * 30 + t * 3;
        if (r < 10) {
            int ii = (int)s[0];
            v = ii ? E[ii * 10 + r] : 0.0f;
        } else if (r < 20) {
            int jj = (int)s[1];
            v = jj ? E[jj * 10 + (r - 10)] : 0.0f;
        } else {
            int ii = (int)s[0];
            if (ii) {
                float diff = 0.7f * (float)(r - 19) - s[2];
                v = __expf(-diff * diff);
            }
        }
    }
    feat[idx] = __float2half(v);
}

// ---- fp16 tensor-core GEMM (8 warps, warp tile 32x128) ----
// C = relu(A[BM,K] @ Bt[n][k]^T + bias); EPI=0 stores half [*,1024]; EPI=1 fuses W3 dot.
#define BM 128
#define BN 256
#define BK 32
#define RSTR 80                          // smem row stride in bytes (64B data + 16B pad)
#define ASTAGE (BM * RSTR)               // 10240 B
#define BSTAGE (BN * RSTR)               // 20480 B
#define STAGE (ASTAGE + BSTAGE)
#define SMEM_BYTES (2 * STAGE + 2 * BN * 4)

template <int EPI>
__global__ void __launch_bounds__(256, 1) gemm_kernel(
    const __half* __restrict__ A, int lda, int K,
    const __half* __restrict__ Bt,    // [1024][K] half (n-major)
    const float* __restrict__ bias,   // [1024]
    const float* __restrict__ W3,     // [1024] (EPI==1)
    void* __restrict__ CoutV)
{
    extern __shared__ char smem[];
    uint32_t sbase;
    asm("{ .reg .u64 t; cvta.to.shared.u64 t, %1; cvt.u32.u64 %0, t; }"
        : "=r"(sbase) : "l"(smem));
    float* sBias = (float*)(smem + 2 * STAGE);
    float* sW3   = sBias + BN;

    const int tid  = threadIdx.x;
    const int lane = tid & 31;
    const int wid  = tid >> 5;
    const int wm   = wid & 3;        // 4 warp rows of 32
    const int wn   = wid >> 2;       // 2 warp cols of 128
    const int g    = lane >> 2;      // 0..7
    const int t    = lane & 3;       // 0..3
    const int lr   = lane & 7;
    const int m0   = blockIdx.y * BM;
    const int n0   = blockIdx.x * BN;

    float acc[2][16][4];
    #pragma unroll
    for (int i = 0; i < 2; i++)
        #pragma unroll
        for (int j = 0; j < 16; j++)
            #pragma unroll
            for (int k = 0; k < 4; k++) acc[i][j][k] = 0.0f;

    const int KT = K / BK;

    auto issue = [&](int kt, int buf) {
        int k0 = kt * BK;
        uint32_t ab = sbase + buf * STAGE;
        uint32_t bb = ab + ASTAGE;
        #pragma unroll
        for (int i = 0; i < 2; i++) {                 // A: 512 chunks of 16B
            int idx = tid + (i << 8);
            int row = idx >> 2, c = idx & 3;
            cp16(ab + row * RSTR + c * 16,
                 A + (size_t)(m0 + row) * lda + k0 + c * 8);
        }
        #pragma unroll
        for (int i = 0; i < 4; i++) {                 // B: 1024 chunks of 16B
            int idx = tid + (i << 8);
            int row = idx >> 2, c = idx & 3;
            cp16(bb + row * RSTR + c * 16,
                 Bt + (size_t)(n0 + row) * K + k0 + c * 8);
        }
    };

    auto compute = [&](int buf) {
        uint32_t ab = sbase + buf * STAGE;
        uint32_t bb = ab + ASTAGE;
        #pragma unroll
        for (int ks = 0; ks < 2; ks++) {              // two k-steps of 16
            const int cb = ks * 2;                    // 16B-chunk base
            uint32_t a[2][4];
            #pragma unroll
            for (int ms = 0; ms < 2; ms++) {
                int row = wm * 32 + ms * 16 + lr + ((lane >> 3) & 1) * 8;
                int ch  = cb + (lane >> 4);
                ldsm4(a[ms], ab + row * RSTR + ch * 16);
            }
            #pragma unroll
            for (int np = 0; np < 8; np++) {          // pairs of n8 tiles
                uint32_t bfr[4];
                int row = wn * 128 + np * 16 + lr + (lane >> 4) * 8;
                int ch  = cb + ((lane >> 3) & 1);
                ldsm4(bfr, bb + row * RSTR + ch * 16);
                mma16(acc[0][2 * np],     a[0], bfr[0], bfr[1]);
                mma16(acc[0][2 * np + 1], a[0], bfr[2], bfr[3]);
                mma16(acc[1][2 * np],     a[1], bfr[0], bfr[1]);
                mma16(acc[1][2 * np + 1], a[1], bfr[2], bfr[3]);
            }
        }
    };

    issue(0, 0);
    CP_COMMIT();
    for (int kt = 0; kt < KT; kt++) {
        int cur = kt & 1;
        if (kt + 1 < KT) { issue(kt + 1, cur ^ 1); CP_COMMIT(); CP_WAIT1(); }
        else             { CP_WAIT0(); }
        __syncthreads();
        compute(cur);
        __syncthreads();
    }

    for (int i = tid; i < BN; i += 256) {
        sBias[i] = bias[n0 + i];
        if (EPI == 1) sW3[i] = W3[n0 + i];
    }
    __syncthreads();

    if (EPI == 0) {
        __half* Cout = (__half*)CoutV;
        #pragma unroll
        for (int ms = 0; ms < 2; ms++) {
            int row = m0 + wm * 32 + ms * 16 + g;
            #pragma unroll
            for (int ns = 0; ns < 16; ns++) {
                int cl  = wn * 128 + ns * 8 + t * 2;
                int col = n0 + cl;
                __half2 v0 = __floats2half2_rn(
                    fmaxf(acc[ms][ns][0] + sBias[cl],     0.0f),
                    fmaxf(acc[ms][ns][1] + sBias[cl + 1], 0.0f));
                __half2 v1 = __floats2half2_rn(
                    fmaxf(acc[ms][ns][2] + sBias[cl],     0.0f),
                    fmaxf(acc[ms][ns][3] + sBias[cl + 1], 0.0f));
                *(__half2*)&Cout[(size_t)row * HID + col]       = v0;
                *(__half2*)&Cout[(size_t)(row + 8) * HID + col] = v1;
            }
        }
    } else {
        float* Cout = (float*)CoutV;
        float racc[2][2] = {{0.0f, 0.0f}, {0.0f, 0.0f}};
        #pragma unroll
        for (int ms = 0; ms < 2; ms++) {
            #pragma unroll
            for (int ns = 0; ns < 16; ns++) {
                int cl = wn * 128 + ns * 8 + t * 2;
                racc[ms][0] += fmaxf(acc[ms][ns][0] + sBias[cl],     0.0f) * sW3[cl]
                             + fmaxf(acc[ms][ns][1] + sBias[cl + 1], 0.0f) * sW3[cl + 1];
                racc[ms][1] += fmaxf(acc[ms][ns][2] + sBias[cl],     0.0f) * sW3[cl]
                             + fmaxf(acc[ms][ns][3] + sBias[cl + 1], 0.0f) * sW3[cl + 1];
            }
        }
        #pragma unroll
        for (int ms = 0; ms < 2; ms++) {
            #pragma unroll
            for (int rp = 0; rp < 2; rp++) {
                float p = racc[ms][rp];
                p += __shfl_xor_sync(0xffffffffu, p, 1);
                p += __shfl_xor_sync(0xffffffffu, p, 2);
                if (t == 0)
                    atomicAdd(&Cout[m0 + wm * 32 + ms * 16 + rp * 8 + g], p);
            }
        }
    }
}

// ---- launch ----
extern "C" void kernel_launch(void* const* d_in, const int* in_sizes, int n_in,
                              void* d_out, int out_size) {
    const float* structures = (const float*)d_in[0];
    const float* E  = (const float*)d_in[1];
    const float* W1 = (const float*)d_in[2];
    const float* b1 = (const float*)d_in[3];
    const float* W2 = (const float*)d_in[4];
    const float* b2 = (const float*)d_in[5];
    const float* W3 = (const float*)d_in[6];
    const float* b3 = (const float*)d_in[7];
    float* out = (float*)d_out;

    __half *feat, *h1, *w1t, *w2t;
    cudaGetSymbolAddress((void**)&feat, g_feat);
    cudaGetSymbolAddress((void**)&h1,   g_h1);
    cudaGetSymbolAddress((void**)&w1t,  g_w1t);
    cudaGetSymbolAddress((void**)&w2t,  g_w2t);

    cudaFuncSetAttribute(gemm_kernel<0>, cudaFuncAttributeMaxDynamicSharedMemorySize, SMEM_BYTES);
    cudaFuncSetAttribute(gemm_kernel<1>, cudaFuncAttributeMaxDynamicSharedMemorySize, SMEM_BYTES);

    prep_w1t_kernel<<<(HID * KF + 255) / 256, 256>>>(W1, w1t);
    prep_w2t_kernel<<<(HID * HID + 255) / 256, 256>>>(W2, w2t);
    init_out_kernel<<<(BSZ + 255) / 256, 256>>>(out, b3);
    feat_kernel<<<(BSZ * KF + 511) / 512, 512>>>(structures, E, feat);

    dim3 grid(HID / BN, BSZ / BM);   // (4, 1024)
    gemm_kernel<0><<<grid, 256, SMEM_BYTES>>>(feat, KF, KF, w1t, b1, nullptr, (void*)h1);
    gemm_kernel<1><<<grid, 256, SMEM_BYTES>>>(h1, HID, HID, w2t, b2, W3, (void*)out);
}

// round 8
// speedup vs baseline: 2.1913x; 1.2120x over previous
#include <cuda_runtime.h>
#include <cuda_fp16.h>
#include <math.h>
#include <stdint.h>

#define BSZ 131072
#define TTR 10
#define KF 320          // padded feature dim (300 -> 320)
#define HID 1024
#define NUM_ELEM 118

// ---- scratch (device globals; no runtime allocation) ----
__device__ __half g_feat[(size_t)BSZ * KF];
__device__ __half g_h1[(size_t)BSZ * HID];
__device__ __half g_w1t[(size_t)HID * KF];    // W1^T [n][k], zero-padded
__device__ __half g_w2t[(size_t)HID * HID];   // W2^T [n][k]

// ---- helpers ----
__device__ __forceinline__ void mma16(float* c, const uint32_t* a,
                                      uint32_t b0, uint32_t b1) {
    asm volatile(
        "mma.sync.aligned.m16n8k16.row.col.f32.f16.f16.f32 "
        "{%0,%1,%2,%3}, {%4,%5,%6,%7}, {%8,%9}, {%0,%1,%2,%3};"
        : "+f"(c[0]), "+f"(c[1]), "+f"(c[2]), "+f"(c[3])
        : "r"(a[0]), "r"(a[1]), "r"(a[2]), "r"(a[3]), "r"(b0), "r"(b1));
}
__device__ __forceinline__ void ldsm4(uint32_t* r, uint32_t addr) {
    asm volatile("ldmatrix.sync.aligned.m8n8.x4.shared.b16 {%0,%1,%2,%3}, [%4];"
                 : "=r"(r[0]), "=r"(r[1]), "=r"(r[2]), "=r"(r[3]) : "r"(addr));
}
__device__ __forceinline__ void cp16(uint32_t dst, const void* src) {
    asm volatile("cp.async.cg.shared.global [%0], [%1], 16;" :: "r"(dst), "l"(src));
}
#define CP_COMMIT() asm volatile("cp.async.commit_group;")
#define CP_WAIT1()  asm volatile("cp.async.wait_group 1;")
#define CP_WAIT0()  asm volatile("cp.async.wait_group 0;")

// ---- prep: transpose weights to [n][k] half ----
__global__ void prep_w1t_kernel(const float* __restrict__ W1, __half* __restrict__ w1t) {
    int i = blockIdx.x * blockDim.x + threadIdx.x;
    if (i >= HID * KF) return;
    int n = i / KF, k = i - n * KF;
    w1t[i] = (k < 300) ? __float2half(W1[(size_t)k * HID + n]) : __half(0.0f);
}
__global__ void prep_w2t_kernel(const float* __restrict__ W2, __half* __restrict__ w2t) {
    int i = blockIdx.x * blockDim.x + threadIdx.x;
    if (i >= HID * HID) return;
    int n = i >> 10, k = i & 1023;
    w2t[i] = __float2half(W2[(size_t)k * HID + n]);
}
__global__ void init_out_kernel(float* __restrict__ out, const float* __restrict__ b3) {
    int i = blockIdx.x * blockDim.x + threadIdx.x;
    if (i < BSZ) out[i] = b3[0];
}

// ---- features: one warp per structure row (shfl hoisted: all lanes participate) ----
__global__ void feat_kernel(const float* __restrict__ structures,
                            const float* __restrict__ E,
                            __half* __restrict__ feat) {
    __shared__ float sE[NUM_ELEM * 10];
    for (int i = threadIdx.x; i < NUM_ELEM * 10; i += blockDim.x) sE[i] = E[i];
    __syncthreads();

    int wrow = (blockIdx.x * blockDim.x + threadIdx.x) >> 5;
    if (wrow >= BSZ) return;
    int lane = threadIdx.x & 31;

    float sv = 0.0f;
    if (lane < 30) sv = structures[(size_t)wrow * 30 + lane];

    __half* o = feat + (size_t)wrow * KF;

    #pragma unroll
    for (int i = 0; i < 10; i++) {
        int c = lane + 32 * i;
        int cc = c < 299 ? c : 299;          // clamp so shfl src lane is valid
        int t = cc / 30;
        int r = cc - t * 30;
        // ALL lanes execute the shuffles (uniform participation, full mask OK)
        float s0 = __shfl_sync(0xffffffffu, sv, 3 * t);
        float s1 = __shfl_sync(0xffffffffu, sv, 3 * t + 1);
        float s2 = __shfl_sync(0xffffffffu, sv, 3 * t + 2);
        float v = 0.0f;
        if (c < 300) {
            int ii = (int)s0;
            int jj = (int)s1;
            if (r < 10) {
                v = ii ? sE[ii * 10 + r] : 0.0f;
            } else if (r < 20) {
                v = jj ? sE[jj * 10 + (r - 10)] : 0.0f;
            } else if (ii) {
                float diff = 0.7f * (float)(r - 19) - s2;
                v = __expf(-diff * diff);
            }
        }
        o[c] = __float2half(v);
    }
}

// ---- fp16 tensor-core GEMM: BK=64, 3-stage cp.async, 1 sync per k-tile ----
#define BM 128
#define BN 256
#define BK 64
#define RSTR 144                         // 128B data + 16B pad per row
#define ASTAGE (BM * RSTR)               // 18432 B
#define BSTAGE (BN * RSTR)               // 36864 B
#define STAGE (ASTAGE + BSTAGE)          // 55296 B
#define NSTG 3
#define SMEM_BYTES (NSTG * STAGE + 2 * BN * 4)

template <int EPI>
__global__ void __launch_bounds__(256, 1) gemm_kernel(
    const __half* __restrict__ A, int lda, int K,
    const __half* __restrict__ Bt,    // [1024][K] half (n-major)
    const float* __restrict__ bias,
    const float* __restrict__ W3,
    void* __restrict__ CoutV)
{
    extern __shared__ char smem[];
    uint32_t sbase;
    asm("{ .reg .u64 t; cvta.to.shared.u64 t, %1; cvt.u32.u64 %0, t; }"
        : "=r"(sbase) : "l"(smem));
    float* sBias = (float*)(smem + NSTG * STAGE);
    float* sW3   = sBias + BN;

    const int tid  = threadIdx.x;
    const int lane = tid & 31;
    const int wid  = tid >> 5;
    const int wm   = wid & 3;        // 4 warp rows of 32
    const int wn   = wid >> 2;       // 2 warp cols of 128
    const int g    = lane >> 2;
    const int t    = lane & 3;
    const int lr   = lane & 7;
    const int m0   = blockIdx.y * BM;
    const int n0   = blockIdx.x * BN;

    float acc[2][16][4];
    #pragma unroll
    for (int i = 0; i < 2; i++)
        #pragma unroll
        for (int j = 0; j < 16; j++)
            #pragma unroll
            for (int k = 0; k < 4; k++) acc[i][j][k] = 0.0f;

    const int KT = K / BK;

    auto issue = [&](int kt, int buf) {
        int k0 = kt * BK;
        uint32_t ab = sbase + buf * STAGE;
        uint32_t bb = ab + ASTAGE;
        #pragma unroll
        for (int i = 0; i < 4; i++) {                 // A: 1024 chunks of 16B
            int idx = tid + (i << 8);
            int row = idx >> 3, c = idx & 7;
            cp16(ab + row * RSTR + c * 16,
                 A + (size_t)(m0 + row) * lda + k0 + c * 8);
        }
        #pragma unroll
        for (int i = 0; i < 8; i++) {                 // B: 2048 chunks of 16B
            int idx = tid + (i << 8);
            int row = idx >> 3, c = idx & 7;
            cp16(bb + row * RSTR + c * 16,
                 Bt + (size_t)(n0 + row) * K + k0 + c * 8);
        }
    };

    auto compute = [&](int buf) {
        uint32_t ab = sbase + buf * STAGE;
        uint32_t bb = ab + ASTAGE;
        #pragma unroll
        for (int ks = 0; ks < 4; ks++) {              // four k-steps of 16
            const int cb = ks * 2;
            uint32_t a[2][4];
            #pragma unroll
            for (int ms = 0; ms < 2; ms++) {
                int row = wm * 32 + ms * 16 + lr + ((lane >> 3) & 1) * 8;
                int ch  = cb + (lane >> 4);
                ldsm4(a[ms], ab + row * RSTR + ch * 16);
            }
            #pragma unroll
            for (int np = 0; np < 8; np++) {
                uint32_t bfr[4];
                int row = wn * 128 + np * 16 + lr + (lane >> 4) * 8;
                int ch  = cb + ((lane >> 3) & 1);
                ldsm4(bfr, bb + row * RSTR + ch * 16);
                mma16(acc[0][2 * np],     a[0], bfr[0], bfr[1]);
                mma16(acc[0][2 * np + 1], a[0], bfr[2], bfr[3]);
                mma16(acc[1][2 * np],     a[1], bfr[0], bfr[1]);
                mma16(acc[1][2 * np + 1], a[1], bfr[2], bfr[3]);
            }
        }
    };

    issue(0, 0); CP_COMMIT();
    issue(1, 1); CP_COMMIT();

    for (int kt = 0; kt < KT; kt++) {
        int cur = kt - (kt / NSTG) * NSTG;            // kt % 3
        if (kt + 1 < KT) CP_WAIT1(); else CP_WAIT0();
        __syncthreads();
        if (kt + 2 < KT) {
            int nb = kt + 2;
            issue(nb, nb - (nb / NSTG) * NSTG);
            CP_COMMIT();
        }
        compute(cur);
    }

    for (int i = tid; i < BN; i += 256) {
        sBias[i] = bias[n0 + i];
        if (EPI == 1) sW3[i] = W3[n0 + i];
    }
    __syncthreads();

    if (EPI == 0) {
        __half* Cout = (__half*)CoutV;
        #pragma unroll
        for (int ms = 0; ms < 2; ms++) {
            int row = m0 + wm * 32 + ms * 16 + g;
            #pragma unroll
            for (int ns = 0; ns < 16; ns++) {
                int cl  = wn * 128 + ns * 8 + t * 2;
                int col = n0 + cl;
                __half2 v0 = __floats2half2_rn(
                    fmaxf(acc[ms][ns][0] + sBias[cl],     0.0f),
                    fmaxf(acc[ms][ns][1] + sBias[cl + 1], 0.0f));
                __half2 v1 = __floats2half2_rn(
                    fmaxf(acc[ms][ns][2] + sBias[cl],     0.0f),
                    fmaxf(acc[ms][ns][3] + sBias[cl + 1], 0.0f));
                *(__half2*)&Cout[(size_t)row * HID + col]       = v0;
                *(__half2*)&Cout[(size_t)(row + 8) * HID + col] = v1;
            }
        }
    } else {
        float* Cout = (float*)CoutV;
        float racc[2][2] = {{0.0f, 0.0f}, {0.0f, 0.0f}};
        #pragma unroll
        for (int ms = 0; ms < 2; ms++) {
            #pragma unroll
            for (int ns = 0; ns < 16; ns++) {
                int cl = wn * 128 + ns * 8 + t * 2;
                racc[ms][0] += fmaxf(acc[ms][ns][0] + sBias[cl],     0.0f) * sW3[cl]
                             + fmaxf(acc[ms][ns][1] + sBias[cl + 1], 0.0f) * sW3[cl + 1];
                racc[ms][1] += fmaxf(acc[ms][ns][2] + sBias[cl],     0.0f) * sW3[cl]
                             + fmaxf(acc[ms][ns][3] + sBias[cl + 1], 0.0f) * sW3[cl + 1];
            }
        }
        #pragma unroll
        for (int ms = 0; ms < 2; ms++) {
            #pragma unroll
            for (int rp = 0; rp < 2; rp++) {
                float p = racc[ms][rp];
                p += __shfl_xor_sync(0xffffffffu, p, 1);
                p += __shfl_xor_sync(0xffffffffu, p, 2);
                if (t == 0)
                    atomicAdd(&Cout[m0 + wm * 32 + ms * 16 + rp * 8 + g], p);
            }
        }
    }
}

// ---- launch ----
extern "C" void kernel_launch(void* const* d_in, const int* in_sizes, int n_in,
                              void* d_out, int out_size) {
    const float* structures = (const float*)d_in[0];
    const float* E  = (const float*)d_in[1];
    const float* W1 = (const float*)d_in[2];
    const float* b1 = (const float*)d_in[3];
    const float* W2 = (const float*)d_in[4];
    const float* b2 = (const float*)d_in[5];
    const float* W3 = (const float*)d_in[6];
    const float* b3 = (const float*)d_in[7];
    float* out = (float*)d_out;

    __half *feat, *h1, *w1t, *w2t;
    cudaGetSymbolAddress((void**)&feat, g_feat);
    cudaGetSymbolAddress((void**)&h1,   g_h1);
    cudaGetSymbolAddress((void**)&w1t,  g_w1t);
    cudaGetSymbolAddress((void**)&w2t,  g_w2t);

    cudaFuncSetAttribute(gemm_kernel<0>, cudaFuncAttributeMaxDynamicSharedMemorySize, SMEM_BYTES);
    cudaFuncSetAttribute(gemm_kernel<1>, cudaFuncAttributeMaxDynamicSharedMemorySize, SMEM_BYTES);

    prep_w1t_kernel<<<(HID * KF + 255) / 256, 256>>>(W1, w1t);
    prep_w2t_kernel<<<(HID * HID + 255) / 256, 256>>>(W2, w2t);
    init_out_kernel<<<(BSZ + 255) / 256, 256>>>(out, b3);
    feat_kernel<<<(BSZ * 32 + 255) / 256, 256>>>(structures, E, feat);

    dim3 grid(HID / BN, BSZ / BM);   // (4, 1024)
    gemm_kernel<0><<<grid, 256, SMEM_BYTES>>>(feat, KF, KF, w1t, b1, nullptr, (void*)h1);
    gemm_kernel<1><<<grid, 256, SMEM_BYTES>>>(h1, HID, HID, w2t, b2, W3, (void*)out);
}

// round 9
// speedup vs baseline: 2.3499x; 1.0724x over previous
#include <cuda_runtime.h>
#include <cuda_fp16.h>
#include <math.h>
#include <stdint.h>

#define BSZ 131072
#define TTR 10
#define KF 320          // padded feature dim (300 -> 320)
#define HID 1024
#define NUM_ELEM 118

// ---- scratch (device globals; no runtime allocation) ----
__device__ __half g_feat[(size_t)BSZ * KF];
__device__ __half g_h1[(size_t)BSZ * HID];
__device__ __half g_w1t[(size_t)HID * KF];    // W1^T [n][k], zero-padded
__device__ __half g_w2t[(size_t)HID * HID];   // W2^T [n][k]

// ---- helpers ----
__device__ __forceinline__ void mma16(float* c, const uint32_t* a,
                                      uint32_t b0, uint32_t b1) {
    asm volatile(
        "mma.sync.aligned.m16n8k16.row.col.f32.f16.f16.f32 "
        "{%0,%1,%2,%3}, {%4,%5,%6,%7}, {%8,%9}, {%0,%1,%2,%3};"
        : "+f"(c[0]), "+f"(c[1]), "+f"(c[2]), "+f"(c[3])
        : "r"(a[0]), "r"(a[1]), "r"(a[2]), "r"(a[3]), "r"(b0), "r"(b1));
}
__device__ __forceinline__ void ldsm4(uint32_t* r, uint32_t addr) {
    asm volatile("ldmatrix.sync.aligned.m8n8.x4.shared.b16 {%0,%1,%2,%3}, [%4];"
                 : "=r"(r[0]), "=r"(r[1]), "=r"(r[2]), "=r"(r[3]) : "r"(addr));
}
__device__ __forceinline__ void cp16(uint32_t dst, const void* src) {
    asm volatile("cp.async.cg.shared.global [%0], [%1], 16;" :: "r"(dst), "l"(src));
}
#define CP_COMMIT() asm volatile("cp.async.commit_group;")
#define CP_WAIT1()  asm volatile("cp.async.wait_group 1;")
#define CP_WAIT0()  asm volatile("cp.async.wait_group 0;")

// ---- prep: transpose weights to [n][k] half ----
__global__ void prep_w1t_kernel(const float* __restrict__ W1, __half* __restrict__ w1t) {
    int i = blockIdx.x * blockDim.x + threadIdx.x;
    if (i >= HID * KF) return;
    int n = i / KF, k = i - n * KF;
    w1t[i] = (k < 300) ? __float2half(W1[(size_t)k * HID + n]) : __half(0.0f);
}
__global__ void prep_w2t_kernel(const float* __restrict__ W2, __half* __restrict__ w2t) {
    int i = blockIdx.x * blockDim.x + threadIdx.x;
    if (i >= HID * HID) return;
    int n = i >> 10, k = i & 1023;
    w2t[i] = __float2half(W2[(size_t)k * HID + n]);
}
__global__ void init_out_kernel(float* __restrict__ out, const float* __restrict__ b3) {
    int i = blockIdx.x * blockDim.x + threadIdx.x;
    if (i < BSZ) out[i] = b3[0];
}

// ---- features: one warp per structure row (all lanes participate in shfl) ----
__global__ void feat_kernel(const float* __restrict__ structures,
                            const float* __restrict__ E,
                            __half* __restrict__ feat) {
    __shared__ float sE[NUM_ELEM * 10];
    for (int i = threadIdx.x; i < NUM_ELEM * 10; i += blockDim.x) sE[i] = E[i];
    __syncthreads();

    int wrow = (blockIdx.x * blockDim.x + threadIdx.x) >> 5;
    if (wrow >= BSZ) return;
    int lane = threadIdx.x & 31;

    float sv = 0.0f;
    if (lane < 30) sv = structures[(size_t)wrow * 30 + lane];

    __half* o = feat + (size_t)wrow * KF;

    #pragma unroll
    for (int i = 0; i < 10; i++) {
        int c = lane + 32 * i;
        int cc = c < 299 ? c : 299;
        int t = cc / 30;
        int r = cc - t * 30;
        float s0 = __shfl_sync(0xffffffffu, sv, 3 * t);
        float s1 = __shfl_sync(0xffffffffu, sv, 3 * t + 1);
        float s2 = __shfl_sync(0xffffffffu, sv, 3 * t + 2);
        float v = 0.0f;
        if (c < 300) {
            int ii = (int)s0;
            int jj = (int)s1;
            if (r < 10) {
                v = ii ? sE[ii * 10 + r] : 0.0f;
            } else if (r < 20) {
                v = jj ? sE[jj * 10 + (r - 10)] : 0.0f;
            } else if (ii) {
                float diff = 0.7f * (float)(r - 19) - s2;
                v = __expf(-diff * diff);
            }
        }
        o[c] = __float2half(v);
    }
}

// ---- fp16 GEMM: BM=128, BN=128, warp 32x64, 2 CTAs/SM, 3-stage cp.async ----
#define BM 128
#define BN 128
#define BK 64
#define RSTR 144                         // 128B data + 16B pad per row
#define ASTAGE (BM * RSTR)               // 18432 B
#define BSTAGE (BN * RSTR)               // 18432 B
#define STAGE (ASTAGE + BSTAGE)          // 36864 B
#define NSTG 3
#define SMEM_BYTES (NSTG * STAGE + 2 * BN * 4)   // 111616 B -> 2 CTAs/SM

template <int EPI>
__global__ void __launch_bounds__(256, 2) gemm_kernel(
    const __half* __restrict__ A, int lda, int K,
    const __half* __restrict__ Bt,    // [1024][K] half (n-major)
    const float* __restrict__ bias,
    const float* __restrict__ W3,
    void* __restrict__ CoutV)
{
    extern __shared__ char smem[];
    uint32_t sbase;
    asm("{ .reg .u64 t; cvta.to.shared.u64 t, %1; cvt.u32.u64 %0, t; }"
        : "=r"(sbase) : "l"(smem));
    float* sBias = (float*)(smem + NSTG * STAGE);
    float* sW3   = sBias + BN;

    const int tid  = threadIdx.x;
    const int lane = tid & 31;
    const int wid  = tid >> 5;
    const int wm   = wid & 3;        // 4 warp rows of 32
    const int wn   = wid >> 2;       // 2 warp cols of 64
    const int g    = lane >> 2;
    const int t    = lane & 3;
    const int lr   = lane & 7;
    const int m0   = blockIdx.y * BM;
    const int n0   = blockIdx.x * BN;

    float acc[2][8][4];
    #pragma unroll
    for (int i = 0; i < 2; i++)
        #pragma unroll
        for (int j = 0; j < 8; j++)
            #pragma unroll
            for (int k = 0; k < 4; k++) acc[i][j][k] = 0.0f;

    const int KT = K / BK;

    auto issue = [&](int kt, int buf) {
        int k0 = kt * BK;
        uint32_t ab = sbase + buf * STAGE;
        uint32_t bb = ab + ASTAGE;
        #pragma unroll
        for (int i = 0; i < 4; i++) {                 // A: 1024 chunks of 16B
            int idx = tid + (i << 8);
            int row = idx >> 3, c = idx & 7;
            cp16(ab + row * RSTR + c * 16,
                 A + (size_t)(m0 + row) * lda + k0 + c * 8);
        }
        #pragma unroll
        for (int i = 0; i < 4; i++) {                 // B: 1024 chunks of 16B
            int idx = tid + (i << 8);
            int row = idx >> 3, c = idx & 7;
            cp16(bb + row * RSTR + c * 16,
                 Bt + (size_t)(n0 + row) * K + k0 + c * 8);
        }
    };

    auto compute = [&](int buf) {
        uint32_t ab = sbase + buf * STAGE;
        uint32_t bb = ab + ASTAGE;
        #pragma unroll
        for (int ks = 0; ks < 4; ks++) {              // four k-steps of 16
            const int cb = ks * 2;
            uint32_t a[2][4];
            #pragma unroll
            for (int ms = 0; ms < 2; ms++) {
                int row = wm * 32 + ms * 16 + lr + ((lane >> 3) & 1) * 8;
                int ch  = cb + (lane >> 4);
                ldsm4(a[ms], ab + row * RSTR + ch * 16);
            }
            #pragma unroll
            for (int np = 0; np < 4; np++) {
                uint32_t bfr[4];
                int row = wn * 64 + np * 16 + lr + (lane >> 4) * 8;
                int ch  = cb + ((lane >> 3) & 1);
                ldsm4(bfr, bb + row * RSTR + ch * 16);
                mma16(acc[0][2 * np],     a[0], bfr[0], bfr[1]);
                mma16(acc[0][2 * np + 1], a[0], bfr[2], bfr[3]);
                mma16(acc[1][2 * np],     a[1], bfr[0], bfr[1]);
                mma16(acc[1][2 * np + 1], a[1], bfr[2], bfr[3]);
            }
        }
    };

    issue(0, 0); CP_COMMIT();
    issue(1, 1); CP_COMMIT();

    for (int kt = 0; kt < KT; kt++) {
        int cur = kt - (kt / NSTG) * NSTG;            // kt % 3
        if (kt + 1 < KT) CP_WAIT1(); else CP_WAIT0();
        __syncthreads();
        if (kt + 2 < KT) {
            int nb = kt + 2;
            issue(nb, nb - (nb / NSTG) * NSTG);
            CP_COMMIT();
        }
        compute(cur);
    }

    for (int i = tid; i < BN; i += 256) {
        sBias[i] = bias[n0 + i];
        if (EPI == 1) sW3[i] = W3[n0 + i];
    }
    __syncthreads();

    if (EPI == 0) {
        __half* Cout = (__half*)CoutV;
        #pragma unroll
        for (int ms = 0; ms < 2; ms++) {
            int row = m0 + wm * 32 + ms * 16 + g;
            #pragma unroll
            for (int ns = 0; ns < 8; ns++) {
                int cl  = wn * 64 + ns * 8 + t * 2;
                int col = n0 + cl;
                __half2 v0 = __floats2half2_rn(
                    fmaxf(acc[ms][ns][0] + sBias[cl],     0.0f),
                    fmaxf(acc[ms][ns][1] + sBias[cl + 1], 0.0f));
                __half2 v1 = __floats2half2_rn(
                    fmaxf(acc[ms][ns][2] + sBias[cl],     0.0f),
                    fmaxf(acc[ms][ns][3] + sBias[cl + 1], 0.0f));
                *(__half2*)&Cout[(size_t)row * HID + col]       = v0;
                *(__half2*)&Cout[(size_t)(row + 8) * HID + col] = v1;
            }
        }
    } else {
        float* Cout = (float*)CoutV;
        float racc[2][2] = {{0.0f, 0.0f}, {0.0f, 0.0f}};
        #pragma unroll
        for (int ms = 0; ms < 2; ms++) {
            #pragma unroll
            for (int ns = 0; ns < 8; ns++) {
                int cl = wn * 64 + ns * 8 + t * 2;
                racc[ms][0] += fmaxf(acc[ms][ns][0] + sBias[cl],     0.0f) * sW3[cl]
                             + fmaxf(acc[ms][ns][1] + sBias[cl + 1], 0.0f) * sW3[cl + 1];
                racc[ms][1] += fmaxf(acc[ms][ns][2] + sBias[cl],     0.0f) * sW3[cl]
                             + fmaxf(acc[ms][ns][3] + sBias[cl + 1], 0.0f) * sW3[cl + 1];
            }
        }
        #pragma unroll
        for (int ms = 0; ms < 2; ms++) {
            #pragma unroll
            for (int rp = 0; rp < 2; rp++) {
                float p = racc[ms][rp];
                p += __shfl_xor_sync(0xffffffffu, p, 1);
                p += __shfl_xor_sync(0xffffffffu, p, 2);
                if (t == 0)
                    atomicAdd(&Cout[m0 + wm * 32 + ms * 16 + rp * 8 + g], p);
            }
        }
    }
}

// ---- launch ----
extern "C" void kernel_launch(void* const* d_in, const int* in_sizes, int n_in,
                              void* d_out, int out_size) {
    const float* structures = (const float*)d_in[0];
    const float* E  = (const float*)d_in[1];
    const float* W1 = (const float*)d_in[2];
    const float* b1 = (const float*)d_in[3];
    const float* W2 = (const float*)d_in[4];
    const float* b2 = (const float*)d_in[5];
    const float* W3 = (const float*)d_in[6];
    const float* b3 = (const float*)d_in[7];
    float* out = (float*)d_out;

    __half *feat, *h1, *w1t, *w2t;
    cudaGetSymbolAddress((void**)&feat, g_feat);
    cudaGetSymbolAddress((void**)&h1,   g_h1);
    cudaGetSymbolAddress((void**)&w1t,  g_w1t);
    cudaGetSymbolAddress((void**)&w2t,  g_w2t);

    cudaFuncSetAttribute(gemm_kernel<0>, cudaFuncAttributeMaxDynamicSharedMemorySize, SMEM_BYTES);
    cudaFuncSetAttribute(gemm_kernel<1>, cudaFuncAttributeMaxDynamicSharedMemorySize, SMEM_BYTES);

    prep_w1t_kernel<<<(HID * KF + 255) / 256, 256>>>(W1, w1t);
    prep_w2t_kernel<<<(HID * HID + 255) / 256, 256>>>(W2, w2t);
    init_out_kernel<<<(BSZ + 255) / 256, 256>>>(out, b3);
    feat_kernel<<<(BSZ * 32 + 255) / 256, 256>>>(structures, E, feat);

    dim3 grid(HID / BN, BSZ / BM);   // (8, 1024)
    gemm_kernel<0><<<grid, 256, SMEM_BYTES>>>(feat, KF, KF, w1t, b1, nullptr, (void*)h1);
    gemm_kernel<1><<<grid, 256, SMEM_BYTES>>>(h1, HID, HID, w2t, b2, W3, (void*)out);
}